// round 1
// baseline (speedup 1.0000x reference)
#include <cuda_runtime.h>
#include <cuda_bf16.h>

typedef unsigned long long ull;

// ---------------- scratch (no allocation allowed) ----------------
__device__ float g_mods[16 * 5 * 512];   // [b][layer][gam|bet]
__device__ float g_loss[16];             // per-b sum of squared diffs over stages

// ---------------- f32x2 helpers ----------------
__device__ __forceinline__ ull dupf(float x) {
    ull r;
    asm("mov.b64 %0, {%1, %1};" : "=l"(r) : "f"(x));
    return r;
}
__device__ __forceinline__ ull fma2(ull a, ull b, ull c) {
    ull d;
    asm("fma.rn.f32x2 %0, %1, %2, %3;" : "=l"(d) : "l"(a), "l"(b), "l"(c));
    return d;
}
__device__ __forceinline__ float2 unpk(ull v) {
    float lo, hi;
    asm("mov.b64 {%0, %1}, %2;" : "=f"(lo), "=f"(hi) : "l"(v));
    float2 r; r.x = lo; r.y = hi; return r;
}

// =================================================================
// Kernel 1: residual VQ + FiLM mods.  grid=16 (one block per b), 256 thr
// =================================================================
__global__ void vq_kernel(const int* __restrict__ lidx,
                          const float* __restrict__ latents,
                          const float* __restrict__ emb,
                          const float* __restrict__ mod_W,
                          const float* __restrict__ mod_b) {
    __shared__ float r[256];
    __shared__ float zsum[256];
    __shared__ float redv[256];
    __shared__ int   redi[256];

    const int b = blockIdx.x;
    const int t = threadIdx.x;

    const int img = lidx[b];
    const float* lp = latents + (size_t)img * 4 * 256;
    float z = lp[t] + lp[256 + t] + lp[512 + t] + lp[768 + t];
    r[t] = z;
    zsum[t] = 0.f;
    __syncthreads();

    float loss = 0.f;

    for (int s = 0; s < 4; ++s) {
        // distances for codes t, 256+t, 512+t, 768+t  (||E||^2 - 2 E.r)
        float best = 3.4e38f;
        int   bi   = 0;
        for (int cc = 0; cc < 4; ++cc) {
            const int c = cc * 256 + t;
            const float4* E4 = reinterpret_cast<const float4*>(
                emb + ((size_t)s * 1024 + c) * 256);
            float s1 = 0.f, s2 = 0.f;
            #pragma unroll 8
            for (int d4 = 0; d4 < 64; ++d4) {
                float4 e = E4[d4];
                const float* rr = r + d4 * 4;
                s1 = fmaf(e.x, e.x, fmaf(e.y, e.y, fmaf(e.z, e.z, fmaf(e.w, e.w, s1))));
                s2 = fmaf(e.x, rr[0], fmaf(e.y, rr[1], fmaf(e.z, rr[2], fmaf(e.w, rr[3], s2))));
            }
            float sc = s1 - 2.f * s2;
            if (sc < best) { best = sc; bi = c; }   // cc ascending => first index kept
        }
        redv[t] = best; redi[t] = bi;
        __syncthreads();
        for (int off = 128; off; off >>= 1) {
            if (t < off) {
                float ov = redv[t + off]; int oi = redi[t + off];
                if (ov < redv[t] || (ov == redv[t] && oi < redi[t])) {
                    redv[t] = ov; redi[t] = oi;
                }
            }
            __syncthreads();
        }
        const int c = redi[0];
        const float e = emb[((size_t)s * 1024 + c) * 256 + t];
        const float diff = e - r[t];
        loss += diff * diff;
        zsum[t] += e;
        __syncthreads();           // argmin result consumed before reuse
        r[t] = r[t] - e;
        __syncthreads();           // residual update visible to next stage
    }

    // reduce loss over the 256 dims
    redv[t] = loss;
    __syncthreads();
    for (int off = 128; off; off >>= 1) {
        if (t < off) redv[t] += redv[t + off];
        __syncthreads();
    }
    if (t == 0) g_loss[b] = redv[0];
    __syncthreads();

    // FiLM mods: g_mods[b][l][h] = sum_d zsum[d] * mod_W[l][d][h] + mod_b[l][h]
    for (int l = 0; l < 5; ++l) {
        for (int hh = 0; hh < 2; ++hh) {
            const int h = hh * 256 + t;
            float a = mod_b[l * 512 + h];
            const float* Wp = mod_W + (size_t)l * 256 * 512 + h;
            #pragma unroll 4
            for (int d = 0; d < 256; ++d)
                a = fmaf(zsum[d], Wp[(size_t)d * 512], a);
            g_mods[(b * 5 + l) * 512 + h] = a;
        }
    }
}

// =================================================================
// Kernel 2: finalize vq_loss -> d_out[out_size-1]
// vq_loss = CC/(NV*B*LD) * sum = sum / 65536
// =================================================================
__global__ void loss_kernel(float* out, int out_size) {
    if (threadIdx.x == 0) {
        float s = 0.f;
        #pragma unroll
        for (int i = 0; i < 16; ++i) s += g_loss[i];
        out[out_size - 1] = s * (1.0f / 65536.0f);
    }
}

// =================================================================
// Kernel 3: fused SIREN decoder.
// grid = (32 tiles, 16 b), 512 threads, M_TILE=128 rows per CTA.
// Thread tile: 8 m-rows x 8 n-cols (split frag nA=nt*4, nB=128+nt*4),
// 32 f32x2 accumulators paired along n.
// =================================================================
__global__ __launch_bounds__(512, 1)
void dec_kernel(const float* __restrict__ coords,
                const float* __restrict__ W0g,
                const float* __restrict__ b0g,
                const float* __restrict__ Whg,
                const float* __restrict__ bhg,
                const float* __restrict__ Wlg,
                const float* __restrict__ blg,
                float* __restrict__ out) {
    extern __shared__ float sm[];
    float* xs   = sm;            // 128*256 = 32768 floats
    float* wb   = xs + 32768;    // 32*256  =  8192
    float* film = wb + 8192;     // 5*512   =  2560
    float* w0s  = film + 2560;   // 768  (W0[2][256] + b0[256])
    float* cs   = w0s + 768;     // 128*2 coords

    const int b      = blockIdx.y;
    const int m_base = blockIdx.x * 128;
    const int t  = threadIdx.x;
    const int nt = t & 31;       // 32 n-tiles, lanes of a warp span all nt
    const int mt = t >> 5;       // 16 m-tiles, one per warp
    const int m0 = mt * 8;
    const int nA = nt * 4;
    const int nB = 128 + nt * 4;
    const int nt2 = nt * 2;      // ull index of nA pair

    // ---- stage constants ----
    for (int i = t; i < 2560; i += 512) film[i] = g_mods[b * 2560 + i];
    for (int i = t; i < 768;  i += 512) w0s[i] = (i < 512) ? W0g[i] : b0g[i - 512];
    if (t < 256) cs[t] = coords[((size_t)b * 4096 + m_base) * 2 + t];
    __syncthreads();

    // ---- layer 0: x = sin(30*(coords@W0 + b0)) ----
    for (int idx = t; idx < 128 * 256; idx += 512) {
        const int m = idx >> 8, n = idx & 255;
        float pre = fmaf(cs[2 * m], w0s[n], fmaf(cs[2 * m + 1], w0s[256 + n], w0s[512 + n]));
        xs[m * 256 + n] = sinf(30.0f * pre);
    }

    // ---- 4 hidden layers ----
    for (int l = 0; l < 4; ++l) {
        const float* W = Whg + (size_t)l * 65536;

        ull acc[8][4];
        #pragma unroll
        for (int mi = 0; mi < 8; ++mi)
            #pragma unroll
            for (int j = 0; j < 4; ++j) acc[mi][j] = 0ull;

        for (int kp = 0; kp < 8; ++kp) {
            __syncthreads();  // previous panel / xs writes consumed
            {   // load 32x256 weight panel
                const float4* Wg  = reinterpret_cast<const float4*>(W + kp * 8192);
                float4*       wb4 = reinterpret_cast<float4*>(wb);
                #pragma unroll
                for (int q = 0; q < 4; ++q) wb4[t + q * 512] = Wg[t + q * 512];
            }
            __syncthreads();

            #pragma unroll
            for (int k2 = 0; k2 < 16; ++k2) {
                const int kk = 2 * k2;
                float2 xv[8];
                #pragma unroll
                for (int mi = 0; mi < 8; ++mi)
                    xv[mi] = *reinterpret_cast<const float2*>(
                        xs + (m0 + mi) * 256 + kp * 32 + kk);

                const ull* w0r = reinterpret_cast<const ull*>(wb + kk * 256);
                const ull* w1r = reinterpret_cast<const ull*>(wb + kk * 256 + 256);
                const ull b00 = w0r[nt2],      b01 = w0r[nt2 + 1];
                const ull b02 = w0r[64 + nt2], b03 = w0r[64 + nt2 + 1];
                const ull b10 = w1r[nt2],      b11 = w1r[nt2 + 1];
                const ull b12 = w1r[64 + nt2], b13 = w1r[64 + nt2 + 1];

                #pragma unroll
                for (int mi = 0; mi < 8; ++mi) {
                    const ull a0 = dupf(xv[mi].x);
                    const ull a1 = dupf(xv[mi].y);
                    acc[mi][0] = fma2(a0, b00, fma2(a1, b10, acc[mi][0]));
                    acc[mi][1] = fma2(a0, b01, fma2(a1, b11, acc[mi][1]));
                    acc[mi][2] = fma2(a0, b02, fma2(a1, b12, acc[mi][2]));
                    acc[mi][3] = fma2(a0, b03, fma2(a1, b13, acc[mi][3]));
                }
            }
        }
        __syncthreads();  // all xs reads for this layer done

        // ---- FiLM + sin epilogue; write back into xs ----
        const float* fg = film + (l + 1) * 512;        // gam
        const float* fb = fg + 256;                    // bet
        const float* bhl = bhg + l * 256;
        float gA[4], beA[4], bhA[4], gB[4], beB[4], bhB[4];
        #pragma unroll
        for (int j = 0; j < 4; ++j) {
            gA[j] = 1.0f + fg[nA + j]; beA[j] = fb[nA + j]; bhA[j] = bhl[nA + j];
            gB[j] = 1.0f + fg[nB + j]; beB[j] = fb[nB + j]; bhB[j] = bhl[nB + j];
        }
        #pragma unroll
        for (int mi = 0; mi < 8; ++mi) {
            float4 oA, oB;
            float2 y;
            y = unpk(acc[mi][0]);
            oA.x = sinf(30.0f * fmaf(y.x + bhA[0], gA[0], beA[0]));
            oA.y = sinf(30.0f * fmaf(y.y + bhA[1], gA[1], beA[1]));
            y = unpk(acc[mi][1]);
            oA.z = sinf(30.0f * fmaf(y.x + bhA[2], gA[2], beA[2]));
            oA.w = sinf(30.0f * fmaf(y.y + bhA[3], gA[3], beA[3]));
            y = unpk(acc[mi][2]);
            oB.x = sinf(30.0f * fmaf(y.x + bhB[0], gB[0], beB[0]));
            oB.y = sinf(30.0f * fmaf(y.y + bhB[1], gB[1], beB[1]));
            y = unpk(acc[mi][3]);
            oB.z = sinf(30.0f * fmaf(y.x + bhB[2], gB[2], beB[2]));
            oB.w = sinf(30.0f * fmaf(y.y + bhB[3], gB[3], beB[3]));
            *reinterpret_cast<float4*>(xs + (m0 + mi) * 256 + nA) = oA;
            *reinterpret_cast<float4*>(xs + (m0 + mi) * 256 + nB) = oB;
        }
    }
    __syncthreads();  // last epilogue visible

    // ---- output head: values = x @ Wl + bl  (256 -> 3) ----
    if (t < 384) {
        const int m = t / 3, c = t % 3;
        float a = blg[c];
        const float* xr = xs + m * 256;
        #pragma unroll 8
        for (int d = 0; d < 256; ++d)
            a = fmaf(xr[d], Wlg[d * 3 + c], a);
        out[((size_t)b * 4096 + m_base + m) * 3 + c] = a;
    }
}

// =================================================================
extern "C" void kernel_launch(void* const* d_in, const int* in_sizes, int n_in,
                              void* d_out, int out_size) {
    const float* coords  = (const float*)d_in[0];
    const int*   lidx    = (const int*)  d_in[1];
    const float* latents = (const float*)d_in[2];
    const float* emb     = (const float*)d_in[3];
    const float* mod_W   = (const float*)d_in[4];
    const float* mod_b   = (const float*)d_in[5];
    const float* W0      = (const float*)d_in[6];
    const float* b0      = (const float*)d_in[7];
    const float* Wh      = (const float*)d_in[8];
    const float* bh      = (const float*)d_in[9];
    const float* Wl      = (const float*)d_in[10];
    const float* bl      = (const float*)d_in[11];
    float* out = (float*)d_out;

    vq_kernel<<<16, 256>>>(lidx, latents, emb, mod_W, mod_b);
    loss_kernel<<<1, 32>>>(out, out_size);

    const size_t smem = (32768 + 8192 + 2560 + 768 + 256) * sizeof(float); // 178176 B
    cudaFuncSetAttribute(dec_kernel, cudaFuncAttributeMaxDynamicSharedMemorySize, (int)smem);
    dec_kernel<<<dim3(32, 16), 512, smem>>>(coords, W0, b0, Wh, bh, Wl, bl, out);
}